// round 14
// baseline (speedup 1.0000x reference)
#include <cuda_runtime.h>
#include <cuda_bf16.h>
#include <math.h>
#include <stdint.h>

// Problem constants
#define BATCH 2
#define SEQ 2048
#define DMODEL 2048
#define NHEADS 16
#define HEADDIM 128
#define CACHE 2048
#define TTOT 4096           // CACHE + SEQ
#define MROWS (BATCH*SEQ)   // 4096
#define KVELEMS (BATCH*NHEADS*TTOT*HEADDIM)  // 16777216

// ---------------------------------------------------------------------------
// Scratch (device globals; no allocations allowed)
// ---------------------------------------------------------------------------
__device__ __nv_bfloat16 g_ah[MROWS * DMODEL];   // x hi, later attn-out hi
__device__ __nv_bfloat16 g_al[MROWS * DMODEL];   // x lo, later attn-out lo
__device__ __nv_bfloat16 g_qh[MROWS * DMODEL];
__device__ __nv_bfloat16 g_ql[MROWS * DMODEL];
__device__ __nv_bfloat16 g_wh[4][DMODEL * DMODEL];
__device__ __nv_bfloat16 g_wl[4][DMODEL * DMODEL];
__device__ __nv_bfloat16 g_kh[KVELEMS];
__device__ __nv_bfloat16 g_kl[KVELEMS];
__device__ __nv_bfloat16 g_vh[KVELEMS];
__device__ __nv_bfloat16 g_vl[KVELEMS];

// ---------------------------------------------------------------------------
// Helpers
// ---------------------------------------------------------------------------
__device__ __forceinline__ uint32_t smem_u32(const void* p) {
    uint32_t a;
    asm("{ .reg .u64 t; cvta.to.shared.u64 t, %1; cvt.u32.u64 %0, t; }" : "=r"(a) : "l"(p));
    return a;
}
__device__ __forceinline__ void cp16(void* dst_smem, const void* src) {
    uint32_t d = smem_u32(dst_smem);
    asm volatile("cp.async.cg.shared.global [%0], [%1], 16;" :: "r"(d), "l"(src) : "memory");
}
__device__ __forceinline__ void cp_commit() {
    asm volatile("cp.async.commit_group;" ::: "memory");
}
__device__ __forceinline__ void cp_wait1() {
    asm volatile("cp.async.wait_group 1;" ::: "memory");
}
__device__ __forceinline__ void cp_wait0() {
    asm volatile("cp.async.wait_group 0;" ::: "memory");
}
// D += A*B : m16n8k16 bf16, fp32 accum
__device__ __forceinline__ void mma16816(float* c, const uint32_t* a, const uint32_t* b) {
    asm volatile(
        "mma.sync.aligned.m16n8k16.row.col.f32.bf16.bf16.f32 "
        "{%0,%1,%2,%3}, {%4,%5,%6,%7}, {%8,%9}, {%0,%1,%2,%3};"
        : "+f"(c[0]), "+f"(c[1]), "+f"(c[2]), "+f"(c[3])
        : "r"(a[0]), "r"(a[1]), "r"(a[2]), "r"(a[3]), "r"(b[0]), "r"(b[1]));
}
__device__ __forceinline__ void ldsm_x4(uint32_t* r, uint32_t saddr) {
    asm volatile("ldmatrix.sync.aligned.m8n8.x4.shared.b16 {%0,%1,%2,%3}, [%4];"
                 : "=r"(r[0]), "=r"(r[1]), "=r"(r[2]), "=r"(r[3]) : "r"(saddr));
}
__device__ __forceinline__ void ldsm_x4_trans(uint32_t* r, uint32_t saddr) {
    asm volatile("ldmatrix.sync.aligned.m8n8.x4.trans.shared.b16 {%0,%1,%2,%3}, [%4];"
                 : "=r"(r[0]), "=r"(r[1]), "=r"(r[2]), "=r"(r[3]) : "r"(saddr));
}
// pack pair of floats to bf16x2 hi and residual lo
__device__ __forceinline__ void packsplit(float p0, float p1, uint32_t& hi, uint32_t& lo) {
    __nv_bfloat162 h = __floats2bfloat162_rn(p0, p1);
    float f0 = __low2float(h), f1 = __high2float(h);
    __nv_bfloat162 g = __floats2bfloat162_rn(p0 - f0, p1 - f1);
    hi = *(uint32_t*)&h;
    lo = *(uint32_t*)&g;
}

// ---------------------------------------------------------------------------
// fp32 -> bf16 hi/lo split: x (grid.y==4) and weights (grid.y=0..3)
// ---------------------------------------------------------------------------
__global__ __launch_bounds__(256) void split_all_kernel(
    const float4* __restrict__ x,
    const float4* __restrict__ w0, const float4* __restrict__ w1,
    const float4* __restrict__ w2, const float4* __restrict__ w3,
    __nv_bfloat16* __restrict__ ah, __nv_bfloat16* __restrict__ al,
    __nv_bfloat16* __restrict__ wh, __nv_bfloat16* __restrict__ wl)
{
    const int which = blockIdx.y;
    const float4* in;
    __nv_bfloat16 *hi, *lo;
    int n4;
    if (which == 4) {
        in = x;  hi = ah;  lo = al;  n4 = MROWS * DMODEL / 4;
    } else {
        const float4* ws[4] = {w0, w1, w2, w3};
        in = ws[which];
        hi = wh + (long)which * DMODEL * DMODEL;
        lo = wl + (long)which * DMODEL * DMODEL;
        n4 = DMODEL * DMODEL / 4;
    }
    int i = blockIdx.x * blockDim.x + threadIdx.x;
    if (i >= n4) return;
    float4 v = in[i];
    union { __nv_bfloat16 h[4]; uint2 u; } H, L;
    float f[4] = {v.x, v.y, v.z, v.w};
#pragma unroll
    for (int j = 0; j < 4; j++) {
        __nv_bfloat16 h = __float2bfloat16_rn(f[j]);
        H.h[j] = h;
        L.h[j] = __float2bfloat16_rn(f[j] - __bfloat162float(h));
    }
    *(uint2*)(hi + (long)i * 4) = H.u;
    *(uint2*)(lo + (long)i * 4) = L.u;
}

// ---------------------------------------------------------------------------
// Cache copy + fused split
// ---------------------------------------------------------------------------
__global__ __launch_bounds__(256) void copy_cache_kernel(
    const float4* __restrict__ ck, const float4* __restrict__ cv,
    float4* __restrict__ ko, float4* __restrict__ vo,
    __nv_bfloat16* __restrict__ kh, __nv_bfloat16* __restrict__ kl,
    __nv_bfloat16* __restrict__ vh, __nv_bfloat16* __restrict__ vl)
{
    int i = blockIdx.x * blockDim.x + threadIdx.x;
    const int N4 = BATCH * NHEADS * CACHE * HEADDIM / 4;
    if (i >= N4) return;
    const int per_bh = CACHE * HEADDIM / 4;
    int bh  = i / per_bh;
    int rem = i - bh * per_bh;
    long dst = (long)bh * (TTOT * HEADDIM / 4) + rem;

    float4 k = ck[i], v = cv[i];
    ko[dst] = k;
    vo[dst] = v;

    union { __nv_bfloat16 h[4]; uint2 u; } KH, KL, VH, VL;
    float kf[4] = {k.x, k.y, k.z, k.w};
    float vf[4] = {v.x, v.y, v.z, v.w};
#pragma unroll
    for (int j = 0; j < 4; j++) {
        __nv_bfloat16 h = __float2bfloat16_rn(kf[j]);
        KH.h[j] = h;
        KL.h[j] = __float2bfloat16_rn(kf[j] - __bfloat162float(h));
        __nv_bfloat16 g = __float2bfloat16_rn(vf[j]);
        VH.h[j] = g;
        VL.h[j] = __float2bfloat16_rn(vf[j] - __bfloat162float(g));
    }
    *(uint2*)(kh + dst * 4) = KH.u;
    *(uint2*)(kl + dst * 4) = KL.u;
    *(uint2*)(vh + dst * 4) = VH.u;
    *(uint2*)(vl + dst * 4) = VL.u;
}

// ---------------------------------------------------------------------------
// HMMA GEMM (fp32 via bf16 hi/lo, 3 MMAs). 2-stage cp.async double buffer.
// MMAs issued in passes over 4 independent accumulators (dep distance 8)
// instead of 3 back-to-back on one accumulator (asm volatile blocks reorder).
// Per-accumulator order bh -> bl -> lo*bh preserved -> bitwise identical.
// ---------------------------------------------------------------------------
#define GM_RS    80
#define GM_MAT   (128 * GM_RS)
#define GM_BUF   (4 * GM_MAT)
#define GM_SMEM  (2 * GM_BUF)      // 81920 B -> 2 CTAs/SM
#define GM_KCH   64

__device__ __forceinline__ void gm_issue_chunk(
    char* buf, const __nv_bfloat16* Ah, const __nv_bfloat16* Al,
    const __nv_bfloat16* Bh, const __nv_bfloat16* Bl,
    long m0, long n0, int k0, int tid)
{
    const int row = tid >> 2;
    const int seg = tid & 3;
#pragma unroll
    for (int it = 0; it < 2; it++) {
        int rr = row + it * 64;
        long off = (long)k0 + seg * 8;
        cp16(buf + 0 * GM_MAT + rr * GM_RS + seg * 16, Ah + (m0 + rr) * DMODEL + off);
        cp16(buf + 1 * GM_MAT + rr * GM_RS + seg * 16, Al + (m0 + rr) * DMODEL + off);
        cp16(buf + 2 * GM_MAT + rr * GM_RS + seg * 16, Bh + (n0 + rr) * DMODEL + off);
        cp16(buf + 3 * GM_MAT + rr * GM_RS + seg * 16, Bl + (n0 + rr) * DMODEL + off);
    }
    cp_commit();
}

__global__ __launch_bounds__(256, 2)
void gemm_tc_kernel(const __nv_bfloat16* __restrict__ Ah,
                    const __nv_bfloat16* __restrict__ Al,
                    const __nv_bfloat16* __restrict__ Wh,
                    const __nv_bfloat16* __restrict__ Wl,
                    float* __restrict__ k_out, float* __restrict__ v_out,
                    float* __restrict__ out,
                    __nv_bfloat16* __restrict__ qh, __nv_bfloat16* __restrict__ ql,
                    __nv_bfloat16* __restrict__ kh, __nv_bfloat16* __restrict__ kl,
                    __nv_bfloat16* __restrict__ vh, __nv_bfloat16* __restrict__ vl,
                    int mode)
{
    extern __shared__ char dsm[];
    const int tid  = threadIdx.x;
    const int wid  = tid >> 5;
    const int l    = tid & 31;
    const int wm   = wid >> 2;
    const int wn   = wid & 3;
    const long m0 = (long)blockIdx.y * 128;

    int which;
    long n0;
    const __nv_bfloat16 *Bh, *Bl;
    if (mode == 3) {
        which = blockIdx.x >> 4;
        n0 = (long)(blockIdx.x & 15) * 128;
        Bh = Wh + (long)which * DMODEL * DMODEL;
        Bl = Wl + (long)which * DMODEL * DMODEL;
    } else {
        which = -1;
        n0 = (long)blockIdx.x * 128;
        Bh = Wh;
        Bl = Wl;
    }

    const uint32_t dsm32 = smem_u32(dsm);
    const int fr = l >> 2;
    const int fq = (l & 3) * 2;

    const uint32_t aoff = (uint32_t)((wm * 64 + (l & 15)) * GM_RS + ((l >> 4) << 4));
    const uint32_t boff = (uint32_t)(2 * GM_MAT +
        (wn * 32 + ((l >> 4) << 3) + (l & 7)) * GM_RS + (((l >> 3) & 1) << 4));

    float acc[4][4][4];
#pragma unroll
    for (int i = 0; i < 4; i++)
#pragma unroll
        for (int j = 0; j < 4; j++)
#pragma unroll
            for (int t = 0; t < 4; t++) acc[i][j][t] = 0.f;

    gm_issue_chunk(dsm, Ah, Al, Bh, Bl, m0, n0, 0, tid);

    for (int c = 0; c < GM_KCH; c++) {
        if (c + 1 < GM_KCH)
            gm_issue_chunk(dsm + ((c + 1) & 1) * GM_BUF, Ah, Al, Bh, Bl,
                           m0, n0, (c + 1) * 32, tid);
        if (c + 1 < GM_KCH) cp_wait1(); else cp_wait0();
        __syncthreads();

        const uint32_t sb = dsm32 + (uint32_t)((c & 1) * GM_BUF);
#pragma unroll
        for (int kk = 0; kk < 32; kk += 16) {
            uint32_t ah4[4][4], al4[4][4];
#pragma unroll
            for (int mt = 0; mt < 4; mt++) {
                ldsm_x4(ah4[mt], sb + aoff + mt * 16 * GM_RS + kk * 2);
                ldsm_x4(al4[mt], sb + GM_MAT + aoff + mt * 16 * GM_RS + kk * 2);
            }
#pragma unroll
            for (int p = 0; p < 2; p++) {
                uint32_t bh4[4], bl4[4];
                ldsm_x4(bh4, sb + boff + p * 16 * GM_RS + kk * 2);
                ldsm_x4(bl4, sb + GM_MAT + boff + p * 16 * GM_RS + kk * 2);
                // pass structure: each acc touched once per pass (distance 8)
#pragma unroll
                for (int mt = 0; mt < 4; mt++) mma16816(acc[mt][2*p],   ah4[mt], bh4);
#pragma unroll
                for (int mt = 0; mt < 4; mt++) mma16816(acc[mt][2*p+1], ah4[mt], bh4 + 2);
#pragma unroll
                for (int mt = 0; mt < 4; mt++) mma16816(acc[mt][2*p],   ah4[mt], bl4);
#pragma unroll
                for (int mt = 0; mt < 4; mt++) mma16816(acc[mt][2*p+1], ah4[mt], bl4 + 2);
#pragma unroll
                for (int mt = 0; mt < 4; mt++) mma16816(acc[mt][2*p],   al4[mt], bh4);
#pragma unroll
                for (int mt = 0; mt < 4; mt++) mma16816(acc[mt][2*p+1], al4[mt], bh4 + 2);
            }
        }
        __syncthreads();
    }

    // Epilogue
#pragma unroll
    for (int mt = 0; mt < 4; mt++) {
#pragma unroll
        for (int nt = 0; nt < 4; nt++) {
            long m = m0 + wm * 64 + mt * 16 + fr;
            int  n = (int)n0 + wn * 32 + nt * 8 + fq;
            float* a = acc[mt][nt];
            if (mode == 2) {
                long e = m * DMODEL + n;
                *(float2*)(out + e) = make_float2(a[0], a[1]);
                *(float2*)(out + e + 8 * DMODEL) = make_float2(a[2], a[3]);
            } else if (which == 0) {
                long e = m * DMODEL + n;
                uint32_t h0, l0, h1, l1;
                packsplit(a[0], a[1], h0, l0);
                packsplit(a[2], a[3], h1, l1);
                *(uint32_t*)(qh + e) = h0;
                *(uint32_t*)(ql + e) = l0;
                *(uint32_t*)(qh + e + 8 * DMODEL) = h1;
                *(uint32_t*)(ql + e + 8 * DMODEL) = l1;
            } else {
                float* Cf = (which == 1) ? k_out : v_out;
                __nv_bfloat16* Ch = (which == 1) ? kh : vh;
                __nv_bfloat16* Cl = (which == 1) ? kl : vl;
                int b = (int)(m >> 11), s = (int)(m & 2047);
                int h = n >> 7, dh = n & 127;
                long base = ((long)(b * NHEADS + h) * TTOT + CACHE + s) * HEADDIM + dh;
                *(float2*)(Cf + base) = make_float2(a[0], a[1]);
                *(float2*)(Cf + base + 8 * HEADDIM) = make_float2(a[2], a[3]);
                uint32_t h0, l0, h1, l1;
                packsplit(a[0], a[1], h0, l0);
                packsplit(a[2], a[3], h1, l1);
                *(uint32_t*)(Ch + base) = h0;
                *(uint32_t*)(Cl + base) = l0;
                *(uint32_t*)(Ch + base + 8 * HEADDIM) = h1;
                *(uint32_t*)(Cl + base + 8 * HEADDIM) = l1;
            }
        }
    }
}

// ---------------------------------------------------------------------------
// Flash attention on HMMA (bf16 hi/lo, fp32 accum), persistent CTAs.
// MMA passes interleave the two accumulator slots (dep distance 2).
// ---------------------------------------------------------------------------
#define AT_RS    272
#define AT_QL    34816
#define AT_STG0  69632
#define AT_STGSZ 69632
#define AT_KL    17408
#define AT_VH    34816
#define AT_SMEM  208896
#define AT_NIT   (TTOT / 64)
#define AT_NTILES (BATCH * NHEADS * (SEQ / 128))   // 512
#define AT_GRID  148

__device__ __forceinline__ void at_issue_kv(
    char* dsm, const __nv_bfloat16* Kh, const __nv_bfloat16* Kl,
    const __nv_bfloat16* Vh, const __nv_bfloat16* Vl,
    long kvoff, int it, int tid)
{
    char* stg = dsm + AT_STG0 + (it & 1) * AT_STGSZ;
    const int t0 = it * 64;
#pragma unroll
    for (int i = 0; i < 16; i++) {
        int idx = tid + i * 256;
        int mat = idx >> 10;
        int row = (idx >> 4) & 63;
        int ch  = idx & 15;
        const __nv_bfloat16* src;
        if      (mat == 0) src = Kh;
        else if (mat == 1) src = Kl;
        else if (mat == 2) src = Vh;
        else               src = Vl;
        cp16(stg + mat * 17408 + row * AT_RS + ch * 16,
             src + kvoff + (long)(t0 + row) * HEADDIM + ch * 8);
    }
    cp_commit();
}

__global__ __launch_bounds__(256, 1) void attn_kernel(
    const __nv_bfloat16* __restrict__ Qh, const __nv_bfloat16* __restrict__ Ql,
    const __nv_bfloat16* __restrict__ Kh, const __nv_bfloat16* __restrict__ Kl,
    const __nv_bfloat16* __restrict__ Vh, const __nv_bfloat16* __restrict__ Vl,
    __nv_bfloat16* __restrict__ Oh, __nv_bfloat16* __restrict__ Ol)
{
    extern __shared__ char dsm[];
    const int tid = threadIdx.x;
    const int w  = tid >> 5;
    const int l  = tid & 31;
    const int fr = l >> 2;
    const uint32_t sbase = smem_u32(dsm);
    const float scale = 0.08838834764831845f;

    const uint32_t qoffm = (uint32_t)((w * 16 + (l & 15)) * AT_RS + ((l >> 4) << 4));
    const uint32_t koffm = (uint32_t)((((l >> 4) << 3) + (l & 7)) * AT_RS + (((l >> 3) & 1) << 4));
    const uint32_t voffm = (uint32_t)((l & 15) * AT_RS + ((l >> 4) << 4));

    for (int tile = blockIdx.x; tile < AT_NTILES; tile += AT_GRID) {
        const int bh = tile >> 4;
        const int st = tile & 15;
        const int b  = bh >> 4, h = bh & 15;
        const int s0 = st * 128;

        __syncthreads();   // prior tile's smem reads complete before reuse

        // Issue Q tiles (hi+lo) + KV stages 0,1
        {
            const long qoff = ((long)b * SEQ + s0) * DMODEL + h * HEADDIM;
#pragma unroll
            for (int i = 0; i < 16; i++) {
                int idx = tid + i * 256;
                int mat = idx >> 11;
                int row = (idx >> 4) & 127;
                int ch  = idx & 15;
                const __nv_bfloat16* src = (mat ? Ql : Qh) + qoff + (long)row * DMODEL + ch * 8;
                cp16(dsm + mat * AT_QL + row * AT_RS + ch * 16, src);
            }
        }
        const long kvoff = (long)bh * TTOT * HEADDIM;
        at_issue_kv(dsm, Kh, Kl, Vh, Vl, kvoff, 0, tid);
        at_issue_kv(dsm, Kh, Kl, Vh, Vl, kvoff, 1, tid);

        float m_lo = -INFINITY, m_hi = -INFINITY, l_lo = 0.f, l_hi = 0.f;
        float oacc[16][4];
#pragma unroll
        for (int i = 0; i < 16; i++)
#pragma unroll
            for (int j = 0; j < 4; j++) oacc[i][j] = 0.f;

        for (int it = 0; it < AT_NIT; it++) {
            if (it + 1 < AT_NIT) cp_wait1(); else cp_wait0();
            __syncthreads();

            const uint32_t stg32 = sbase + AT_STG0 + (uint32_t)((it & 1) * AT_STGSZ);

            // ---- S = Q K^T ----
            float sacc[8][4];
#pragma unroll
            for (int i = 0; i < 8; i++)
#pragma unroll
                for (int j = 0; j < 4; j++) sacc[i][j] = 0.f;

#pragma unroll
            for (int ks = 0; ks < 8; ks++) {
                uint32_t aH[4], aL[4];
                ldsm_x4(aH, sbase + qoffm + ks * 32);
                ldsm_x4(aL, sbase + AT_QL + qoffm + ks * 32);
#pragma unroll
                for (int p = 0; p < 4; p++) {
                    uint32_t bH[4], bL[4];
                    ldsm_x4(bH, stg32 + koffm + p * 16 * AT_RS + ks * 32);
                    ldsm_x4(bL, stg32 + AT_KL + koffm + p * 16 * AT_RS + ks * 32);
                    // interleave the two acc slots (dep distance 2)
                    mma16816(sacc[2 * p],     aH, bH);
                    mma16816(sacc[2 * p + 1], aH, bH + 2);
                    mma16816(sacc[2 * p],     aH, bL);
                    mma16816(sacc[2 * p + 1], aH, bL + 2);
                    mma16816(sacc[2 * p],     aL, bH);
                    mma16816(sacc[2 * p + 1], aL, bH + 2);
                }
            }

            // ---- softmax max phase ----
            float mx0 = -INFINITY, mx1 = -INFINITY;
#pragma unroll
            for (int nt = 0; nt < 8; nt++) {
#pragma unroll
                for (int j = 0; j < 4; j++) sacc[nt][j] *= scale;
                mx0 = fmaxf(mx0, fmaxf(sacc[nt][0], sacc[nt][1]));
                mx1 = fmaxf(mx1, fmaxf(sacc[nt][2], sacc[nt][3]));
            }
            mx0 = fmaxf(mx0, __shfl_xor_sync(0xffffffffu, mx0, 1));
            mx0 = fmaxf(mx0, __shfl_xor_sync(0xffffffffu, mx0, 2));
            mx1 = fmaxf(mx1, __shfl_xor_sync(0xffffffffu, mx1, 1));
            mx1 = fmaxf(mx1, __shfl_xor_sync(0xffffffffu, mx1, 2));
            float mn0 = fmaxf(m_lo, mx0), mn1 = fmaxf(m_hi, mx1);
            float al0 = __expf(m_lo - mn0), al1 = __expf(m_hi - mn1);

            // rescale O before accumulation
#pragma unroll
            for (int dt = 0; dt < 16; dt++) {
                oacc[dt][0] *= al0;  oacc[dt][1] *= al0;
                oacc[dt][2] *= al1;  oacc[dt][3] *= al1;
            }

            // ---- per-kt: exp + packsplit + PV MMAs ----
            float sm0 = 0.f, sm1 = 0.f;
            const uint32_t vbase = stg32 + AT_VH + voffm;
#pragma unroll
            for (int kt = 0; kt < 4; kt++) {
                float e00 = __expf(sacc[2 * kt][0] - mn0);
                float e01 = __expf(sacc[2 * kt][1] - mn0);
                float e02 = __expf(sacc[2 * kt][2] - mn1);
                float e03 = __expf(sacc[2 * kt][3] - mn1);
                float e10 = __expf(sacc[2 * kt + 1][0] - mn0);
                float e11 = __expf(sacc[2 * kt + 1][1] - mn0);
                float e12 = __expf(sacc[2 * kt + 1][2] - mn1);
                float e13 = __expf(sacc[2 * kt + 1][3] - mn1);
                sm0 += e00 + e01;  sm1 += e02 + e03;
                sm0 += e10 + e11;  sm1 += e12 + e13;

                uint32_t aPh[4], aPl[4];
                packsplit(e00, e01, aPh[0], aPl[0]);
                packsplit(e02, e03, aPh[1], aPl[1]);
                packsplit(e10, e11, aPh[2], aPl[2]);
                packsplit(e12, e13, aPh[3], aPl[3]);

                uint32_t vrow = vbase + (uint32_t)(kt * 16 * AT_RS);
#pragma unroll
                for (int dt2 = 0; dt2 < 8; dt2++) {
                    uint32_t bh4[4], bl4[4];
                    ldsm_x4_trans(bh4, vrow + dt2 * 32);
                    ldsm_x4_trans(bl4, vrow + AT_KL + dt2 * 32);
                    // interleave the two acc slots (dep distance 2)
                    mma16816(oacc[2 * dt2],     aPh, bh4);
                    mma16816(oacc[2 * dt2 + 1], aPh, bh4 + 2);
                    mma16816(oacc[2 * dt2],     aPh, bl4);
                    mma16816(oacc[2 * dt2 + 1], aPh, bl4 + 2);
                    mma16816(oacc[2 * dt2],     aPl, bh4);
                    mma16816(oacc[2 * dt2 + 1], aPl, bh4 + 2);
                }
            }

            sm0 += __shfl_xor_sync(0xffffffffu, sm0, 1);
            sm0 += __shfl_xor_sync(0xffffffffu, sm0, 2);
            sm1 += __shfl_xor_sync(0xffffffffu, sm1, 1);
            sm1 += __shfl_xor_sync(0xffffffffu, sm1, 2);
            l_lo = l_lo * al0 + sm0;  m_lo = mn0;
            l_hi = l_hi * al1 + sm1;  m_hi = mn1;

            __syncthreads();
            if (it + 2 < AT_NIT)
                at_issue_kv(dsm, Kh, Kl, Vh, Vl, kvoff, it + 2, tid);
        }

        // ---- epilogue: normalize + hi/lo split store ----
        float inv0 = 1.f / l_lo, inv1 = 1.f / l_hi;
        long r0 = ((long)b * SEQ + s0 + w * 16 + fr) * DMODEL + h * HEADDIM + (l & 3) * 2;
#pragma unroll
        for (int dt = 0; dt < 16; dt++) {
            uint32_t h0, l0, h1, l1;
            packsplit(oacc[dt][0] * inv0, oacc[dt][1] * inv0, h0, l0);
            packsplit(oacc[dt][2] * inv1, oacc[dt][3] * inv1, h1, l1);
            *(uint32_t*)(Oh + r0 + dt * 8) = h0;
            *(uint32_t*)(Ol + r0 + dt * 8) = l0;
            *(uint32_t*)(Oh + r0 + 8 * DMODEL + dt * 8) = h1;
            *(uint32_t*)(Ol + r0 + 8 * DMODEL + dt * 8) = l1;
        }
    }
}

// ---------------------------------------------------------------------------
// kernel_launch
// Inputs: x, cached_k, cached_v, W_q, W_k, W_v, W_o
// Output: [ out (B,S,D) | k (B,H,TTOT,Dh) | v (B,H,TTOT,Dh) ]
// ---------------------------------------------------------------------------
extern "C" void kernel_launch(void* const* d_in, const int* in_sizes, int n_in,
                              void* d_out, int out_size)
{
    const float* x  = (const float*)d_in[0];
    const float* ck = (const float*)d_in[1];
    const float* cv = (const float*)d_in[2];
    const float* wts[4] = { (const float*)d_in[3], (const float*)d_in[4],
                            (const float*)d_in[5], (const float*)d_in[6] };

    float* out   = (float*)d_out;
    float* k_out = out + (long)MROWS * DMODEL;
    float* v_out = k_out + (long)KVELEMS;

    __nv_bfloat16 *ah, *al, *qh, *ql, *wh, *wl, *kh, *kl, *vh, *vl;
    cudaGetSymbolAddress((void**)&ah, g_ah);
    cudaGetSymbolAddress((void**)&al, g_al);
    cudaGetSymbolAddress((void**)&qh, g_qh);
    cudaGetSymbolAddress((void**)&ql, g_ql);
    cudaGetSymbolAddress((void**)&wh, g_wh);
    cudaGetSymbolAddress((void**)&wl, g_wl);
    cudaGetSymbolAddress((void**)&kh, g_kh);
    cudaGetSymbolAddress((void**)&kl, g_kl);
    cudaGetSymbolAddress((void**)&vh, g_vh);
    cudaGetSymbolAddress((void**)&vl, g_vl);

    // 1) copy KV cache into outputs + fused hi/lo split
    {
        const int N4 = BATCH * NHEADS * CACHE * HEADDIM / 4;
        copy_cache_kernel<<<(N4 + 255) / 256, 256>>>(
            (const float4*)ck, (const float4*)cv, (float4*)k_out, (float4*)v_out,
            kh, kl, vh, vl);
    }

    // 2) hi/lo splits: x (grid.y=4) and the 4 weights (grid.y=0..3), one launch
    {
        const int xn4 = MROWS * DMODEL / 4;
        split_all_kernel<<<dim3((xn4 + 255) / 256, 5), 256>>>(
            (const float4*)x,
            (const float4*)wts[0], (const float4*)wts[1],
            (const float4*)wts[2], (const float4*)wts[3],
            ah, al, wh, wl);
    }

    // 3) fused Q+K+V projections (one launch, grid 48x32, 2 CTAs/SM)
    cudaFuncSetAttribute(gemm_tc_kernel, cudaFuncAttributeMaxDynamicSharedMemorySize,
                         GM_SMEM);
    gemm_tc_kernel<<<dim3(48, MROWS / 128), 256, GM_SMEM>>>(
        ah, al, wh, wl, k_out, v_out, nullptr,
        qh, ql, kh, kl, vh, vl, 3);

    // 4) attention (HMMA, persistent), writes hi/lo into ah/al
    cudaFuncSetAttribute(attn_kernel, cudaFuncAttributeMaxDynamicSharedMemorySize,
                         AT_SMEM);
    attn_kernel<<<AT_GRID, 256, AT_SMEM>>>(qh, ql, kh, kl, vh, vl, ah, al);

    // 5) O projection
    gemm_tc_kernel<<<dim3(DMODEL / 128, MROWS / 128), 256, GM_SMEM>>>(
        ah, al, wh + 3L * DMODEL * DMODEL, wl + 3L * DMODEL * DMODEL,
        nullptr, nullptr, out,
        nullptr, nullptr, nullptr, nullptr, nullptr, nullptr, 2);
}

// round 15
// speedup vs baseline: 1.0284x; 1.0284x over previous
#include <cuda_runtime.h>
#include <cuda_bf16.h>
#include <math.h>
#include <stdint.h>

// Problem constants
#define BATCH 2
#define SEQ 2048
#define DMODEL 2048
#define NHEADS 16
#define HEADDIM 128
#define CACHE 2048
#define TTOT 4096           // CACHE + SEQ
#define MROWS (BATCH*SEQ)   // 4096
#define KVELEMS (BATCH*NHEADS*TTOT*HEADDIM)  // 16777216

// ---------------------------------------------------------------------------
// Scratch (device globals; no allocations allowed)
// ---------------------------------------------------------------------------
__device__ __nv_bfloat16 g_ah[MROWS * DMODEL];   // x hi, later attn-out hi
__device__ __nv_bfloat16 g_al[MROWS * DMODEL];   // x lo, later attn-out lo
__device__ __nv_bfloat16 g_qh[MROWS * DMODEL];
__device__ __nv_bfloat16 g_ql[MROWS * DMODEL];
__device__ __nv_bfloat16 g_wh[4][DMODEL * DMODEL];
__device__ __nv_bfloat16 g_wl[4][DMODEL * DMODEL];
__device__ __nv_bfloat16 g_kh[KVELEMS];
__device__ __nv_bfloat16 g_kl[KVELEMS];
__device__ __nv_bfloat16 g_vh[KVELEMS];
__device__ __nv_bfloat16 g_vl[KVELEMS];

// ---------------------------------------------------------------------------
// Helpers
// ---------------------------------------------------------------------------
__device__ __forceinline__ uint32_t smem_u32(const void* p) {
    uint32_t a;
    asm("{ .reg .u64 t; cvta.to.shared.u64 t, %1; cvt.u32.u64 %0, t; }" : "=r"(a) : "l"(p));
    return a;
}
__device__ __forceinline__ void cp16(void* dst_smem, const void* src) {
    uint32_t d = smem_u32(dst_smem);
    asm volatile("cp.async.cg.shared.global [%0], [%1], 16;" :: "r"(d), "l"(src) : "memory");
}
__device__ __forceinline__ void cp_commit() {
    asm volatile("cp.async.commit_group;" ::: "memory");
}
__device__ __forceinline__ void cp_wait0() {
    asm volatile("cp.async.wait_group 0;" ::: "memory");
}
// D += A*B : m16n8k16 bf16, fp32 accum
__device__ __forceinline__ void mma16816(float* c, const uint32_t* a, const uint32_t* b) {
    asm volatile(
        "mma.sync.aligned.m16n8k16.row.col.f32.bf16.bf16.f32 "
        "{%0,%1,%2,%3}, {%4,%5,%6,%7}, {%8,%9}, {%0,%1,%2,%3};"
        : "+f"(c[0]), "+f"(c[1]), "+f"(c[2]), "+f"(c[3])
        : "r"(a[0]), "r"(a[1]), "r"(a[2]), "r"(a[3]), "r"(b[0]), "r"(b[1]));
}
__device__ __forceinline__ void ldsm_x4(uint32_t* r, uint32_t saddr) {
    asm volatile("ldmatrix.sync.aligned.m8n8.x4.shared.b16 {%0,%1,%2,%3}, [%4];"
                 : "=r"(r[0]), "=r"(r[1]), "=r"(r[2]), "=r"(r[3]) : "r"(saddr));
}
__device__ __forceinline__ void ldsm_x4_trans(uint32_t* r, uint32_t saddr) {
    asm volatile("ldmatrix.sync.aligned.m8n8.x4.trans.shared.b16 {%0,%1,%2,%3}, [%4];"
                 : "=r"(r[0]), "=r"(r[1]), "=r"(r[2]), "=r"(r[3]) : "r"(saddr));
}
// pack pair of floats to bf16x2 hi and residual lo
__device__ __forceinline__ void packsplit(float p0, float p1, uint32_t& hi, uint32_t& lo) {
    __nv_bfloat162 h = __floats2bfloat162_rn(p0, p1);
    float f0 = __low2float(h), f1 = __high2float(h);
    __nv_bfloat162 g = __floats2bfloat162_rn(p0 - f0, p1 - f1);
    hi = *(uint32_t*)&h;
    lo = *(uint32_t*)&g;
}

// ---------------------------------------------------------------------------
// fp32 -> bf16 hi/lo split: x (grid.y==4) and weights (grid.y=0..3)
// ---------------------------------------------------------------------------
__global__ __launch_bounds__(256) void split_all_kernel(
    const float4* __restrict__ x,
    const float4* __restrict__ w0, const float4* __restrict__ w1,
    const float4* __restrict__ w2, const float4* __restrict__ w3,
    __nv_bfloat16* __restrict__ ah, __nv_bfloat16* __restrict__ al,
    __nv_bfloat16* __restrict__ wh, __nv_bfloat16* __restrict__ wl)
{
    const int which = blockIdx.y;
    const float4* in;
    __nv_bfloat16 *hi, *lo;
    int n4;
    if (which == 4) {
        in = x;  hi = ah;  lo = al;  n4 = MROWS * DMODEL / 4;
    } else {
        const float4* ws[4] = {w0, w1, w2, w3};
        in = ws[which];
        hi = wh + (long)which * DMODEL * DMODEL;
        lo = wl + (long)which * DMODEL * DMODEL;
        n4 = DMODEL * DMODEL / 4;
    }
    int i = blockIdx.x * blockDim.x + threadIdx.x;
    if (i >= n4) return;
    float4 v = in[i];
    union { __nv_bfloat16 h[4]; uint2 u; } H, L;
    float f[4] = {v.x, v.y, v.z, v.w};
#pragma unroll
    for (int j = 0; j < 4; j++) {
        __nv_bfloat16 h = __float2bfloat16_rn(f[j]);
        H.h[j] = h;
        L.h[j] = __float2bfloat16_rn(f[j] - __bfloat162float(h));
    }
    *(uint2*)(hi + (long)i * 4) = H.u;
    *(uint2*)(lo + (long)i * 4) = L.u;
}

// ---------------------------------------------------------------------------
// HMMA GEMM (fp32 via bf16 hi/lo, 3 MMAs). Single-barrier double-buffered
// cp.async pipeline (wait0 -> sync -> issue-next -> compute).
// mode 3: fused QKV, grid (80,32): x<48 GEMM (which = x>>4), x>=48 cache-copy.
// mode 2: O projection, grid (16,32): fp32 row-major.
// ---------------------------------------------------------------------------
#define GM_RS    80
#define GM_MAT   (128 * GM_RS)
#define GM_BUF   (4 * GM_MAT)
#define GM_SMEM  (2 * GM_BUF)      // 81920 B -> 2 CTAs/SM
#define GM_KCH   64

__device__ __forceinline__ void gm_issue_chunk(
    char* buf, const __nv_bfloat16* Ah, const __nv_bfloat16* Al,
    const __nv_bfloat16* Bh, const __nv_bfloat16* Bl,
    long m0, long n0, int k0, int tid)
{
    const int row = tid >> 2;
    const int seg = tid & 3;
#pragma unroll
    for (int it = 0; it < 2; it++) {
        int rr = row + it * 64;
        long off = (long)k0 + seg * 8;
        cp16(buf + 0 * GM_MAT + rr * GM_RS + seg * 16, Ah + (m0 + rr) * DMODEL + off);
        cp16(buf + 1 * GM_MAT + rr * GM_RS + seg * 16, Al + (m0 + rr) * DMODEL + off);
        cp16(buf + 2 * GM_MAT + rr * GM_RS + seg * 16, Bh + (n0 + rr) * DMODEL + off);
        cp16(buf + 3 * GM_MAT + rr * GM_RS + seg * 16, Bl + (n0 + rr) * DMODEL + off);
    }
    cp_commit();
}

__global__ __launch_bounds__(256, 2)
void gemm_tc_kernel(const __nv_bfloat16* __restrict__ Ah,
                    const __nv_bfloat16* __restrict__ Al,
                    const __nv_bfloat16* __restrict__ Wh,
                    const __nv_bfloat16* __restrict__ Wl,
                    const float4* __restrict__ ck4, const float4* __restrict__ cv4,
                    float* __restrict__ k_out, float* __restrict__ v_out,
                    float* __restrict__ out,
                    __nv_bfloat16* __restrict__ qh, __nv_bfloat16* __restrict__ ql,
                    __nv_bfloat16* __restrict__ kh, __nv_bfloat16* __restrict__ kl,
                    __nv_bfloat16* __restrict__ vh, __nv_bfloat16* __restrict__ vl,
                    int mode)
{
    extern __shared__ char dsm[];
    const int tid  = threadIdx.x;

    // ---- fused cache-copy blocks (mode 3, blockIdx.x in [48,80)) ----
    if (mode == 3 && blockIdx.x >= 48) {
        const int slice = (blockIdx.x - 48) * gridDim.y + blockIdx.y;  // 0..1023
        const int per_bh = CACHE * HEADDIM / 4;
#pragma unroll
        for (int t = 0; t < 8; t++) {
            int i = slice * 2048 + t * 256 + tid;
            int bh  = i / per_bh;
            int rem = i - bh * per_bh;
            long dst = (long)bh * (TTOT * HEADDIM / 4) + rem;
            float4 k = ck4[i], v = cv4[i];
            ((float4*)k_out)[dst] = k;
            ((float4*)v_out)[dst] = v;
            union { __nv_bfloat16 h[4]; uint2 u; } KH, KL, VH, VL;
            float kf[4] = {k.x, k.y, k.z, k.w};
            float vf[4] = {v.x, v.y, v.z, v.w};
#pragma unroll
            for (int j = 0; j < 4; j++) {
                __nv_bfloat16 h = __float2bfloat16_rn(kf[j]);
                KH.h[j] = h;
                KL.h[j] = __float2bfloat16_rn(kf[j] - __bfloat162float(h));
                __nv_bfloat16 g = __float2bfloat16_rn(vf[j]);
                VH.h[j] = g;
                VL.h[j] = __float2bfloat16_rn(vf[j] - __bfloat162float(g));
            }
            *(uint2*)(kh + dst * 4) = KH.u;
            *(uint2*)(kl + dst * 4) = KL.u;
            *(uint2*)(vh + dst * 4) = VH.u;
            *(uint2*)(vl + dst * 4) = VL.u;
        }
        return;
    }

    const int wid  = tid >> 5;
    const int l    = tid & 31;
    const int wm   = wid >> 2;
    const int wn   = wid & 3;
    const long m0 = (long)blockIdx.y * 128;

    int which;
    long n0;
    const __nv_bfloat16 *Bh, *Bl;
    if (mode == 3) {
        which = blockIdx.x >> 4;
        n0 = (long)(blockIdx.x & 15) * 128;
        Bh = Wh + (long)which * DMODEL * DMODEL;
        Bl = Wl + (long)which * DMODEL * DMODEL;
    } else {
        which = -1;
        n0 = (long)blockIdx.x * 128;
        Bh = Wh;
        Bl = Wl;
    }

    const uint32_t dsm32 = smem_u32(dsm);
    const int fr = l >> 2;
    const int fq = (l & 3) * 2;

    const uint32_t aoff = (uint32_t)((wm * 64 + (l & 15)) * GM_RS + ((l >> 4) << 4));
    const uint32_t boff = (uint32_t)(2 * GM_MAT +
        (wn * 32 + ((l >> 4) << 3) + (l & 7)) * GM_RS + (((l >> 3) & 1) << 4));

    float acc[4][4][4];
#pragma unroll
    for (int i = 0; i < 4; i++)
#pragma unroll
        for (int j = 0; j < 4; j++)
#pragma unroll
            for (int t = 0; t < 4; t++) acc[i][j][t] = 0.f;

    gm_issue_chunk(dsm, Ah, Al, Bh, Bl, m0, n0, 0, tid);

    for (int c = 0; c < GM_KCH; c++) {
        cp_wait0();
        __syncthreads();
        if (c + 1 < GM_KCH)
            gm_issue_chunk(dsm + ((c + 1) & 1) * GM_BUF, Ah, Al, Bh, Bl,
                           m0, n0, (c + 1) * 32, tid);

        const uint32_t sb = dsm32 + (uint32_t)((c & 1) * GM_BUF);
#pragma unroll
        for (int kk = 0; kk < 32; kk += 16) {
            uint32_t ah4[4][4], al4[4][4];
#pragma unroll
            for (int mt = 0; mt < 4; mt++) {
                ldsm_x4(ah4[mt], sb + aoff + mt * 16 * GM_RS + kk * 2);
                ldsm_x4(al4[mt], sb + GM_MAT + aoff + mt * 16 * GM_RS + kk * 2);
            }
#pragma unroll
            for (int p = 0; p < 2; p++) {
                uint32_t bh4[4], bl4[4];
                ldsm_x4(bh4, sb + boff + p * 16 * GM_RS + kk * 2);
                ldsm_x4(bl4, sb + GM_MAT + boff + p * 16 * GM_RS + kk * 2);
#pragma unroll
                for (int mt = 0; mt < 4; mt++) mma16816(acc[mt][2*p],   ah4[mt], bh4);
#pragma unroll
                for (int mt = 0; mt < 4; mt++) mma16816(acc[mt][2*p+1], ah4[mt], bh4 + 2);
#pragma unroll
                for (int mt = 0; mt < 4; mt++) mma16816(acc[mt][2*p],   ah4[mt], bl4);
#pragma unroll
                for (int mt = 0; mt < 4; mt++) mma16816(acc[mt][2*p+1], ah4[mt], bl4 + 2);
#pragma unroll
                for (int mt = 0; mt < 4; mt++) mma16816(acc[mt][2*p],   al4[mt], bh4);
#pragma unroll
                for (int mt = 0; mt < 4; mt++) mma16816(acc[mt][2*p+1], al4[mt], bh4 + 2);
            }
        }
    }

    // Epilogue
#pragma unroll
    for (int mt = 0; mt < 4; mt++) {
#pragma unroll
        for (int nt = 0; nt < 4; nt++) {
            long m = m0 + wm * 64 + mt * 16 + fr;
            int  n = (int)n0 + wn * 32 + nt * 8 + fq;
            float* a = acc[mt][nt];
            if (mode == 2) {
                long e = m * DMODEL + n;
                *(float2*)(out + e) = make_float2(a[0], a[1]);
                *(float2*)(out + e + 8 * DMODEL) = make_float2(a[2], a[3]);
            } else if (which == 0) {
                long e = m * DMODEL + n;
                uint32_t h0, l0, h1, l1;
                packsplit(a[0], a[1], h0, l0);
                packsplit(a[2], a[3], h1, l1);
                *(uint32_t*)(qh + e) = h0;
                *(uint32_t*)(ql + e) = l0;
                *(uint32_t*)(qh + e + 8 * DMODEL) = h1;
                *(uint32_t*)(ql + e + 8 * DMODEL) = l1;
            } else {
                float* Cf = (which == 1) ? k_out : v_out;
                __nv_bfloat16* Ch = (which == 1) ? kh : vh;
                __nv_bfloat16* Cl = (which == 1) ? kl : vl;
                int b = (int)(m >> 11), s = (int)(m & 2047);
                int h = n >> 7, dh = n & 127;
                long base = ((long)(b * NHEADS + h) * TTOT + CACHE + s) * HEADDIM + dh;
                *(float2*)(Cf + base) = make_float2(a[0], a[1]);
                *(float2*)(Cf + base + 8 * HEADDIM) = make_float2(a[2], a[3]);
                uint32_t h0, l0, h1, l1;
                packsplit(a[0], a[1], h0, l0);
                packsplit(a[2], a[3], h1, l1);
                *(uint32_t*)(Ch + base) = h0;
                *(uint32_t*)(Cl + base) = l0;
                *(uint32_t*)(Ch + base + 8 * HEADDIM) = h1;
                *(uint32_t*)(Cl + base + 8 * HEADDIM) = l1;
            }
        }
    }
}

// ---------------------------------------------------------------------------
// Flash attention on HMMA (bf16 hi/lo, fp32 accum), persistent CTAs.
// Single-barrier double-buffered KV pipeline.
// ---------------------------------------------------------------------------
#define AT_RS    272
#define AT_QL    34816
#define AT_STG0  69632
#define AT_STGSZ 69632
#define AT_KL    17408
#define AT_VH    34816
#define AT_SMEM  208896
#define AT_NIT   (TTOT / 64)
#define AT_NTILES (BATCH * NHEADS * (SEQ / 128))   // 512
#define AT_GRID  148

__device__ __forceinline__ void at_issue_kv(
    char* dsm, const __nv_bfloat16* Kh, const __nv_bfloat16* Kl,
    const __nv_bfloat16* Vh, const __nv_bfloat16* Vl,
    long kvoff, int it, int tid)
{
    char* stg = dsm + AT_STG0 + (it & 1) * AT_STGSZ;
    const int t0 = it * 64;
#pragma unroll
    for (int i = 0; i < 16; i++) {
        int idx = tid + i * 256;
        int mat = idx >> 10;
        int row = (idx >> 4) & 63;
        int ch  = idx & 15;
        const __nv_bfloat16* src;
        if      (mat == 0) src = Kh;
        else if (mat == 1) src = Kl;
        else if (mat == 2) src = Vh;
        else               src = Vl;
        cp16(stg + mat * 17408 + row * AT_RS + ch * 16,
             src + kvoff + (long)(t0 + row) * HEADDIM + ch * 8);
    }
    cp_commit();
}

__global__ __launch_bounds__(256, 1) void attn_kernel(
    const __nv_bfloat16* __restrict__ Qh, const __nv_bfloat16* __restrict__ Ql,
    const __nv_bfloat16* __restrict__ Kh, const __nv_bfloat16* __restrict__ Kl,
    const __nv_bfloat16* __restrict__ Vh, const __nv_bfloat16* __restrict__ Vl,
    __nv_bfloat16* __restrict__ Oh, __nv_bfloat16* __restrict__ Ol)
{
    extern __shared__ char dsm[];
    const int tid = threadIdx.x;
    const int w  = tid >> 5;
    const int l  = tid & 31;
    const int fr = l >> 2;
    const uint32_t sbase = smem_u32(dsm);
    const float scale = 0.08838834764831845f;

    const uint32_t qoffm = (uint32_t)((w * 16 + (l & 15)) * AT_RS + ((l >> 4) << 4));
    const uint32_t koffm = (uint32_t)((((l >> 4) << 3) + (l & 7)) * AT_RS + (((l >> 3) & 1) << 4));
    const uint32_t voffm = (uint32_t)((l & 15) * AT_RS + ((l >> 4) << 4));

    for (int tile = blockIdx.x; tile < AT_NTILES; tile += AT_GRID) {
        const int bh = tile >> 4;
        const int st = tile & 15;
        const int b  = bh >> 4, h = bh & 15;
        const int s0 = st * 128;

        __syncthreads();   // prior tile's smem readers done before Q/buf rewrite

        // Issue Q tiles (hi+lo) + KV stage 0
        {
            const long qoff = ((long)b * SEQ + s0) * DMODEL + h * HEADDIM;
#pragma unroll
            for (int i = 0; i < 16; i++) {
                int idx = tid + i * 256;
                int mat = idx >> 11;
                int row = (idx >> 4) & 127;
                int ch  = idx & 15;
                const __nv_bfloat16* src = (mat ? Ql : Qh) + qoff + (long)row * DMODEL + ch * 8;
                cp16(dsm + mat * AT_QL + row * AT_RS + ch * 16, src);
            }
        }
        const long kvoff = (long)bh * TTOT * HEADDIM;
        at_issue_kv(dsm, Kh, Kl, Vh, Vl, kvoff, 0, tid);

        float m_lo = -INFINITY, m_hi = -INFINITY, l_lo = 0.f, l_hi = 0.f;
        float oacc[16][4];
#pragma unroll
        for (int i = 0; i < 16; i++)
#pragma unroll
            for (int j = 0; j < 4; j++) oacc[i][j] = 0.f;

        for (int it = 0; it < AT_NIT; it++) {
            cp_wait0();
            __syncthreads();
            if (it + 1 < AT_NIT)
                at_issue_kv(dsm, Kh, Kl, Vh, Vl, kvoff, it + 1, tid);

            const uint32_t stg32 = sbase + AT_STG0 + (uint32_t)((it & 1) * AT_STGSZ);

            // ---- S = Q K^T ----
            float sacc[8][4];
#pragma unroll
            for (int i = 0; i < 8; i++)
#pragma unroll
                for (int j = 0; j < 4; j++) sacc[i][j] = 0.f;

#pragma unroll
            for (int ks = 0; ks < 8; ks++) {
                uint32_t aH[4], aL[4];
                ldsm_x4(aH, sbase + qoffm + ks * 32);
                ldsm_x4(aL, sbase + AT_QL + qoffm + ks * 32);
#pragma unroll
                for (int p = 0; p < 4; p++) {
                    uint32_t bH[4], bL[4];
                    ldsm_x4(bH, stg32 + koffm + p * 16 * AT_RS + ks * 32);
                    ldsm_x4(bL, stg32 + AT_KL + koffm + p * 16 * AT_RS + ks * 32);
                    mma16816(sacc[2 * p],     aH, bH);
                    mma16816(sacc[2 * p + 1], aH, bH + 2);
                    mma16816(sacc[2 * p],     aH, bL);
                    mma16816(sacc[2 * p + 1], aH, bL + 2);
                    mma16816(sacc[2 * p],     aL, bH);
                    mma16816(sacc[2 * p + 1], aL, bH + 2);
                }
            }

            // ---- softmax max phase ----
            float mx0 = -INFINITY, mx1 = -INFINITY;
#pragma unroll
            for (int nt = 0; nt < 8; nt++) {
#pragma unroll
                for (int j = 0; j < 4; j++) sacc[nt][j] *= scale;
                mx0 = fmaxf(mx0, fmaxf(sacc[nt][0], sacc[nt][1]));
                mx1 = fmaxf(mx1, fmaxf(sacc[nt][2], sacc[nt][3]));
            }
            mx0 = fmaxf(mx0, __shfl_xor_sync(0xffffffffu, mx0, 1));
            mx0 = fmaxf(mx0, __shfl_xor_sync(0xffffffffu, mx0, 2));
            mx1 = fmaxf(mx1, __shfl_xor_sync(0xffffffffu, mx1, 1));
            mx1 = fmaxf(mx1, __shfl_xor_sync(0xffffffffu, mx1, 2));
            float mn0 = fmaxf(m_lo, mx0), mn1 = fmaxf(m_hi, mx1);
            float al0 = __expf(m_lo - mn0), al1 = __expf(m_hi - mn1);

            // rescale O before accumulation
#pragma unroll
            for (int dt = 0; dt < 16; dt++) {
                oacc[dt][0] *= al0;  oacc[dt][1] *= al0;
                oacc[dt][2] *= al1;  oacc[dt][3] *= al1;
            }

            // ---- per-kt: exp + packsplit + PV MMAs ----
            float sm0 = 0.f, sm1 = 0.f;
            const uint32_t vbase = stg32 + AT_VH + voffm;
#pragma unroll
            for (int kt = 0; kt < 4; kt++) {
                float e00 = __expf(sacc[2 * kt][0] - mn0);
                float e01 = __expf(sacc[2 * kt][1] - mn0);
                float e02 = __expf(sacc[2 * kt][2] - mn1);
                float e03 = __expf(sacc[2 * kt][3] - mn1);
                float e10 = __expf(sacc[2 * kt + 1][0] - mn0);
                float e11 = __expf(sacc[2 * kt + 1][1] - mn0);
                float e12 = __expf(sacc[2 * kt + 1][2] - mn1);
                float e13 = __expf(sacc[2 * kt + 1][3] - mn1);
                sm0 += e00 + e01;  sm1 += e02 + e03;
                sm0 += e10 + e11;  sm1 += e12 + e13;

                uint32_t aPh[4], aPl[4];
                packsplit(e00, e01, aPh[0], aPl[0]);
                packsplit(e02, e03, aPh[1], aPl[1]);
                packsplit(e10, e11, aPh[2], aPl[2]);
                packsplit(e12, e13, aPh[3], aPl[3]);

                uint32_t vrow = vbase + (uint32_t)(kt * 16 * AT_RS);
#pragma unroll
                for (int dt2 = 0; dt2 < 8; dt2++) {
                    uint32_t bh4[4], bl4[4];
                    ldsm_x4_trans(bh4, vrow + dt2 * 32);
                    ldsm_x4_trans(bl4, vrow + AT_KL + dt2 * 32);
                    mma16816(oacc[2 * dt2],     aPh, bh4);
                    mma16816(oacc[2 * dt2 + 1], aPh, bh4 + 2);
                    mma16816(oacc[2 * dt2],     aPh, bl4);
                    mma16816(oacc[2 * dt2 + 1], aPh, bl4 + 2);
                    mma16816(oacc[2 * dt2],     aPl, bh4);
                    mma16816(oacc[2 * dt2 + 1], aPl, bh4 + 2);
                }
            }

            sm0 += __shfl_xor_sync(0xffffffffu, sm0, 1);
            sm0 += __shfl_xor_sync(0xffffffffu, sm0, 2);
            sm1 += __shfl_xor_sync(0xffffffffu, sm1, 1);
            sm1 += __shfl_xor_sync(0xffffffffu, sm1, 2);
            l_lo = l_lo * al0 + sm0;  m_lo = mn0;
            l_hi = l_hi * al1 + sm1;  m_hi = mn1;
        }

        // ---- epilogue: normalize + hi/lo split store ----
        float inv0 = 1.f / l_lo, inv1 = 1.f / l_hi;
        long r0 = ((long)b * SEQ + s0 + w * 16 + fr) * DMODEL + h * HEADDIM + (l & 3) * 2;
#pragma unroll
        for (int dt = 0; dt < 16; dt++) {
            uint32_t h0, l0, h1, l1;
            packsplit(oacc[dt][0] * inv0, oacc[dt][1] * inv0, h0, l0);
            packsplit(oacc[dt][2] * inv1, oacc[dt][3] * inv1, h1, l1);
            *(uint32_t*)(Oh + r0 + dt * 8) = h0;
            *(uint32_t*)(Ol + r0 + dt * 8) = l0;
            *(uint32_t*)(Oh + r0 + 8 * DMODEL + dt * 8) = h1;
            *(uint32_t*)(Ol + r0 + 8 * DMODEL + dt * 8) = l1;
        }
    }
}

// ---------------------------------------------------------------------------
// kernel_launch
// Inputs: x, cached_k, cached_v, W_q, W_k, W_v, W_o
// Output: [ out (B,S,D) | k (B,H,TTOT,Dh) | v (B,H,TTOT,Dh) ]
// ---------------------------------------------------------------------------
extern "C" void kernel_launch(void* const* d_in, const int* in_sizes, int n_in,
                              void* d_out, int out_size)
{
    const float* x  = (const float*)d_in[0];
    const float* ck = (const float*)d_in[1];
    const float* cv = (const float*)d_in[2];
    const float* wts[4] = { (const float*)d_in[3], (const float*)d_in[4],
                            (const float*)d_in[5], (const float*)d_in[6] };

    float* out   = (float*)d_out;
    float* k_out = out + (long)MROWS * DMODEL;
    float* v_out = k_out + (long)KVELEMS;

    __nv_bfloat16 *ah, *al, *qh, *ql, *wh, *wl, *kh, *kl, *vh, *vl;
    cudaGetSymbolAddress((void**)&ah, g_ah);
    cudaGetSymbolAddress((void**)&al, g_al);
    cudaGetSymbolAddress((void**)&qh, g_qh);
    cudaGetSymbolAddress((void**)&ql, g_ql);
    cudaGetSymbolAddress((void**)&wh, g_wh);
    cudaGetSymbolAddress((void**)&wl, g_wl);
    cudaGetSymbolAddress((void**)&kh, g_kh);
    cudaGetSymbolAddress((void**)&kl, g_kl);
    cudaGetSymbolAddress((void**)&vh, g_vh);
    cudaGetSymbolAddress((void**)&vl, g_vl);

    // 1) hi/lo splits: x (grid.y=4) and the 4 weights (grid.y=0..3), one launch
    {
        const int xn4 = MROWS * DMODEL / 4;
        split_all_kernel<<<dim3((xn4 + 255) / 256, 5), 256>>>(
            (const float4*)x,
            (const float4*)wts[0], (const float4*)wts[1],
            (const float4*)wts[2], (const float4*)wts[3],
            ah, al, wh, wl);
    }

    // 2) fused Q+K+V projections + cache copy (one launch, grid 80x32)
    cudaFuncSetAttribute(gemm_tc_kernel, cudaFuncAttributeMaxDynamicSharedMemorySize,
                         GM_SMEM);
    gemm_tc_kernel<<<dim3(80, MROWS / 128), 256, GM_SMEM>>>(
        ah, al, wh, wl, (const float4*)ck, (const float4*)cv,
        k_out, v_out, nullptr,
        qh, ql, kh, kl, vh, vl, 3);

    // 3) attention (HMMA, persistent), writes hi/lo into ah/al
    cudaFuncSetAttribute(attn_kernel, cudaFuncAttributeMaxDynamicSharedMemorySize,
                         AT_SMEM);
    attn_kernel<<<AT_GRID, 256, AT_SMEM>>>(qh, ql, kh, kl, vh, vl, ah, al);

    // 4) O projection
    gemm_tc_kernel<<<dim3(DMODEL / 128, MROWS / 128), 256, GM_SMEM>>>(
        ah, al, wh + 3L * DMODEL * DMODEL, wl + 3L * DMODEL * DMODEL,
        nullptr, nullptr, nullptr, nullptr, out,
        nullptr, nullptr, nullptr, nullptr, nullptr, nullptr, 2);
}